// round 15
// baseline (speedup 1.0000x reference)
#include <cuda_runtime.h>
#include <cuda_fp16.h>
#include <cstdint>
#include <math.h>

#define KS 64
#define KM 16
#define TWO_PI 6.28318530717958647692f

#define G     32768          // grid intervals over [-1, 1]
#define TABW  80             // floats per table row: 52 base + 28 delta(fp16x2)
#define TABQ  20             // float4 per row

typedef unsigned long long ull;

// Packed table row (float4 units):
//  q0-3: wgt[16]  q4-7: wx[16]  q8-11: wy[16]  q12: (tr, ldr, pad, pad)
//  q13-19: fp16 deltas, half-linear: wgt d[0..15], wx d[16..31],
//          wy d[32..47], tr d[48], ldr d[49], pad to 56.
__device__ __align__(16) float gTab[(G + 1) * TABW];

// ---------------- packed f32x2 helpers (Blackwell) ----------------
__device__ __forceinline__ ull pk2(float a, float b) {
    ull r; asm("mov.b64 %0, {%1,%2};" : "=l"(r) : "f"(a), "f"(b)); return r;
}
__device__ __forceinline__ void upk2(ull v, float& a, float& b) {
    asm("mov.b64 {%0,%1}, %2;" : "=f"(a), "=f"(b) : "l"(v));
}
#define FMA_X2(d, a, b, c) \
    asm("fma.rn.f32x2 %0, %1, %2, %3;" : "=l"(d) : "l"(a), "l"(b), "l"(c))
#define ADD_X2(d, a, b) \
    asm("add.rn.f32x2 %0, %1, %2;" : "=l"(d) : "l"(a), "l"(b))

__device__ __forceinline__ uint32_t smem_u32(const void* p) {
    uint32_t a;
    asm("{ .reg .u64 t; cvta.to.shared.u64 t, %1; cvt.u32.u64 %0, t; }"
        : "=r"(a) : "l"(p));
    return a;
}

// Fast atan2: octant reduction + deg-11 odd minimax (abs err ~1e-6).
__device__ __forceinline__ float fast_atan2f(float y, float x) {
    float ax = fabsf(x), ay = fabsf(y);
    float mx = fmaxf(ax, ay), mn = fminf(ax, ay);
    float a  = __fdividef(mn, mx);
    float s  = a * a;
    float p  =             -0.0117212f;
    p = fmaf(p, s,  0.05265332f);
    p = fmaf(p, s, -0.11643287f);
    p = fmaf(p, s,  0.19354346f);
    p = fmaf(p, s, -0.33262347f);
    p = fmaf(p, s,  0.99997726f);
    float r = p * a;
    if (ay > ax)  r = 1.57079632679f - r;
    if (x < 0.f)  r = 3.14159265359f - r;
    return (y < 0.f) ? -r : r;
}

// ---------------------------------------------------------------------------
// Table prep: 2 threads per grid point. Thread pair splits the W2 reduction
// dimension (h1 halves) and the W3 output halves; one shfl_xor per j merges
// the partial dot product (commutative add -> identical h2 both threads).
// 64 points per 128-thread block.
// ---------------------------------------------------------------------------
#define PREP_TPB 128
#define PTS_PER_BLOCK (PREP_TPB / 2)

__global__ void __launch_bounds__(PREP_TPB)
table_prep_kernel(const float* __restrict__ tw,
                  const float* __restrict__ thd,
                  const float* __restrict__ td,
                  const float* __restrict__ W1,
                  const float* __restrict__ b1,
                  const float* __restrict__ W2,
                  const float* __restrict__ b2,
                  const float* __restrict__ W3,
                  const float* __restrict__ b3) {
    __shared__ __align__(16) float sW2t[64 * 64];
    __shared__ __align__(16) float sW3[64 * 48];
    __shared__ __align__(16) float sW1[64];
    __shared__ __align__(16) float sb1[64];
    __shared__ __align__(16) float sb2[64];
    __shared__ __align__(16) float sb3[48];
    __shared__ float sxk[KS + 1], syk[KS + 1], sdv[KS + 1];
    __shared__ float scw[KS], sch[KS], stmp[KS];

    int tid = threadIdx.x;

    // ---- weights into smem ----
    for (int i = tid; i < 64 * 64; i += PREP_TPB)
        sW2t[i] = W2[(i & 63) * 64 + (i >> 6)];     // sW2t[j*64+i] = W2[i*64+j]
    for (int i = tid; i < 64 * 48; i += PREP_TPB) sW3[i] = W3[i];
    if (tid < 64) { sW1[tid] = W1[tid]; sb1[tid] = b1[tid]; sb2[tid] = b2[tid]; }
    if (tid < 48) sb3[tid] = b3[tid];

    // ---- knot tables: softmax + cumsum scans (threads 0..63) ----
    if (tid < KS) { scw[tid] = tw[tid]; sch[tid] = thd[tid]; }
    __syncthreads();
    if (tid < KS) stmp[tid] = scw[tid];
    __syncthreads();
    for (int off = 32; off > 0; off >>= 1) {
        if (tid < off) stmp[tid] = fmaxf(stmp[tid], stmp[tid + off]);
        __syncthreads();
    }
    float mw = stmp[0];
    __syncthreads();
    if (tid < KS) stmp[tid] = sch[tid];
    __syncthreads();
    for (int off = 32; off > 0; off >>= 1) {
        if (tid < off) stmp[tid] = fmaxf(stmp[tid], stmp[tid + off]);
        __syncthreads();
    }
    float mh = stmp[0];
    __syncthreads();
    if (tid < KS) { scw[tid] = expf(scw[tid] - mw); sch[tid] = expf(sch[tid] - mh); }
    __syncthreads();
    if (tid < KS) stmp[tid] = scw[tid];
    __syncthreads();
    for (int off = 32; off > 0; off >>= 1) {
        if (tid < off) stmp[tid] += stmp[tid + off];
        __syncthreads();
    }
    float sumw = stmp[0];
    __syncthreads();
    if (tid < KS) stmp[tid] = sch[tid];
    __syncthreads();
    for (int off = 32; off > 0; off >>= 1) {
        if (tid < off) stmp[tid] += stmp[tid + off];
        __syncthreads();
    }
    float sumh = stmp[0];
    __syncthreads();
    for (int off = 1; off < KS; off <<= 1) {
        float vw = 0.f, vh = 0.f;
        if (tid < KS && tid >= off) { vw = scw[tid - off]; vh = sch[tid - off]; }
        __syncthreads();
        if (tid < KS) { scw[tid] += vw; sch[tid] += vh; }
        __syncthreads();
    }
    if (tid < KS) {
        sxk[tid + 1] = fmaf(scw[tid], 2.0f / sumw, -1.0f);
        syk[tid + 1] = fmaf(sch[tid], 2.0f / sumh, -1.0f);
    }
    if (tid == 0) {
        sxk[0] = -1.0f; syk[0] = -1.0f;
        sdv[0] = 1.0f;  sdv[KS] = 1.0f;
    }
    if (tid < KS - 1) {
        float x = td[tid];
        sdv[tid + 1] = fmaxf(x, 0.f) + log1pf(expf(-fabsf(x))) + 0.001f;
    }
    __syncthreads();

    // 2 threads per point; clamp (duplicates write identical bytes; no
    // early return so the pair shuffles stay converged).
    int sub = tid & 1;
    int g   = blockIdx.x * PTS_PER_BLOCK + (tid >> 1);
    g = min(g, G);

    float r = -1.0f + 2.0f * (float)g / (float)G;

    // ---------------- spline (redundant per pair, cheap) ----------------
    int lo = 0, hi = KS + 1;
    while (lo < hi) {
        int mid = (lo + hi) >> 1;
        if (sxk[mid] < r) lo = mid + 1; else hi = mid;
    }
    int k = lo;
    if (k == 0) k = 1;
    if (k == KS + 1) k = KS;
    k -= 1;

    float xk = sxk[k], xn = sxk[k + 1];
    float yk = syk[k], yn = syk[k + 1];
    float dk = sdv[k], dnk = sdv[k + 1];
    float invw = 1.0f / (xn - xk);
    float s_k  = (yn - yk) * invw;
    float eps  = (r - xk) * invw;
    float ome  = 1.0f - eps;
    float eom  = eps * ome;
    float den  = s_k + (dnk + dk - 2.0f * s_k) * eom;
    float tr   = yk + (yn - yk) * (s_k * eps * eps + dk * eom) / den;
    float dtr  = s_k * s_k * (dnk * eps * eps + 2.0f * s_k * eom + dk * ome * ome)
                 / (den * den);

    // ---------------- MLP 1->64->64->48, i-dim split across the pair ----
    // my h1 half: i in [sub*32, sub*32+32) as 16 packed pairs
    ull h1p[16];
    #pragma unroll
    for (int m = 0; m < 16; m++) {
        int i = (sub << 5) + 2 * m;
        float a = fmaxf(fmaf(r, sW1[i],     sb1[i]),     0.0f);
        float b = fmaxf(fmaf(r, sW1[i + 1], sb1[i + 1]), 0.0f);
        h1p[m] = pk2(a, b);
    }

    ull thp[12];   // my half of th: global th[sub*24 .. sub*24+23]
    #pragma unroll
    for (int m = 0; m < 12; m++) thp[m] = 0ULL;

    for (int j = 0; j < 64; j++) {
        const ulonglong2* w2q =
            (const ulonglong2*)&sW2t[j * 64 + (sub << 5)];
        ull a0 = 0ULL, a1 = 0ULL, a2 = 0ULL, a3 = 0ULL;
        #pragma unroll
        for (int q = 0; q < 4; q++) {
            ulonglong2 va = w2q[2 * q];
            ulonglong2 vb = w2q[2 * q + 1];
            FMA_X2(a0, h1p[4 * q + 0], va.x, a0);
            FMA_X2(a1, h1p[4 * q + 1], va.y, a1);
            FMA_X2(a2, h1p[4 * q + 2], vb.x, a2);
            FMA_X2(a3, h1p[4 * q + 3], vb.y, a3);
        }
        ADD_X2(a0, a0, a1);
        ADD_X2(a2, a2, a3);
        ADD_X2(a0, a0, a2);
        float s0, s1;
        upk2(a0, s0, s1);
        float s = s0 + s1;
        float full = s + __shfl_xor_sync(0xffffffffu, s, 1);
        float h2 = fmaxf(full + sb2[j], 0.0f);
        ull h2p = pk2(h2, h2);

        const ulonglong2* w3q =
            (const ulonglong2*)&sW3[j * 48 + sub * 24];
        #pragma unroll
        for (int q = 0; q < 6; q++) {
            ulonglong2 v = w3q[q];
            FMA_X2(thp[2 * q + 0], h2p, v.x, thp[2 * q + 0]);
            FMA_X2(thp[2 * q + 1], h2p, v.y, thp[2 * q + 1]);
        }
    }

    // add my half of b3
    const ull* b3p = (const ull*)sb3;
    #pragma unroll
    for (int m = 0; m < 12; m++) ADD_X2(thp[m], thp[m], b3p[sub * 12 + m]);

    float th[24];
    #pragma unroll
    for (int m = 0; m < 12; m++) upk2(thp[m], th[2 * m], th[2 * m + 1]);

    // ---------------- Mobius preprocessing, split by ownership ----------
    float* row = &gTab[g * TABW];
    if (sub == 0) {
        // th[0..15] = logits, th[16..23] = w pairs k=0..3
        float mx = th[0];
        #pragma unroll
        for (int t = 1; t < KM; t++) mx = fmaxf(mx, th[t]);
        float se = 0.f;
        #pragma unroll
        for (int t = 0; t < KM; t++) {
            th[t] = __expf(th[t] - mx);
            se += th[t];
        }
        float inv_se = 1.0f / se;
        #pragma unroll
        for (int t = 0; t < KM; t++) row[t] = th[t] * inv_se;   // wgt

        #pragma unroll
        for (int kk = 0; kk < 4; kk++) {
            float wa = th[16 + 2 * kk];
            float wb = th[17 + 2 * kk];
            float nr = sqrtf(wa * wa + wb * wb);
            float sc = 0.99f / (1.0f + nr);
            row[16 + kk] = sc * wa;
            row[32 + kk] = sc * wb;
        }
        row[48] = tr;
        row[49] = logf(dtr);
        row[50] = 0.f;
        row[51] = 0.f;
    } else {
        // th[0..23] = global th[24..47] = w pairs k=4..15
        #pragma unroll
        for (int kk = 4; kk < KM; kk++) {
            float wa = th[2 * kk - 8];
            float wb = th[2 * kk - 7];
            float nr = sqrtf(wa * wa + wb * wb);
            float sc = 0.99f / (1.0f + nr);
            row[16 + kk] = sc * wa;
            row[32 + kk] = sc * wb;
        }
    }
}

// ---------------------------------------------------------------------------
// Pack kernel: per-row fp16 deltas (row[g+1] - row[g]) into floats 52..79.
// ---------------------------------------------------------------------------
__global__ void table_pack_kernel() {
    int g = blockIdx.x * blockDim.x + threadIdx.x;
    if (g >= G) return;
    const float* a = &gTab[g * TABW];
    const float* b = &gTab[(g + 1) * TABW];
    __half2* d = (__half2*)(&gTab[g * TABW + 52]);
    #pragma unroll
    for (int e = 0; e < 25; e++) {
        float2 df;
        df.x = b[2 * e]     - a[2 * e];
        df.y = b[2 * e + 1] - a[2 * e + 1];
        d[e] = __float22half2_rn(df);
    }
    #pragma unroll
    for (int e = 25; e < 28; e++) d[e] = __half2half2(__float2half(0.f));
}

// ---------------------------------------------------------------------------
// Main kernel (unchanged from 81.9us version): per-warp SMEM staging via
// cp.async, base + fp16-delta lerp, Mobius with division-free h0.
// ---------------------------------------------------------------------------
#define TPB 64
#define ROWQ 21   // padded float4 stride per point in smem (20 data + 1 pad)

__global__ void __launch_bounds__(TPB)
mobius_lookup_kernel(const float* __restrict__ R,
                     const float* __restrict__ Z,
                     float* __restrict__ out,
                     int N) {
    __shared__ __align__(16) float4 sTab[TPB * ROWQ];   // 21 KB

    int tid   = threadIdx.x;
    int lane  = tid & 31;
    int wbase = tid & ~31;
    int idx0  = blockIdx.x * TPB + tid;
    int idx   = min(idx0, N - 1);

    float r = R[idx];
    float z = Z[idx];

    float u = (r + 1.0f) * ((float)G * 0.5f);
    int i = (int)floorf(u);
    i = max(0, min(G - 1, i));
    float f = u - (float)i;

    // Stage this warp's 32 points with cp.async: one 20-float4 row each,
    // lane-contiguous within each point's row.
    const float4* tab4 = (const float4*)gTab;
    uint32_t sbase = smem_u32(sTab);
    #pragma unroll 10
    for (int it = 0; it < 20; it++) {
        int fl = it * 32 + lane;
        int p  = fl / 20;
        int j  = fl - p * 20;
        int ip = __shfl_sync(0xffffffffu, i, p);
        uint32_t dst = sbase + (uint32_t)(((wbase + p) * ROWQ + j) * 16);
        const float4* src = tab4 + (size_t)ip * TABQ + j;
        asm volatile("cp.async.cg.shared.global [%0], [%1], 16;"
                     :: "r"(dst), "l"(src) : "memory");
    }
    asm volatile("cp.async.commit_group;" ::: "memory");
    asm volatile("cp.async.wait_group 0;" ::: "memory");
    __syncwarp();

    const float4*  q  = &sTab[tid * ROWQ];          // q0..12 base
    const __half2* dh = (const __half2*)(q + 13);   // 28 half2 deltas

    float sz, cz;
    __sincosf(z, &sz, &cz);

    float t_acc = 0.f, dt_acc = 0.f;

    #pragma unroll
    for (int gq = 0; gq < 4; gq++) {
        float4 wgB = q[gq];
        float4 wxB = q[4 + gq];
        float4 wyB = q[8 + gq];
        float2 dg0 = __half22float2(dh[2 * gq]);
        float2 dg1 = __half22float2(dh[2 * gq + 1]);
        float2 dx0 = __half22float2(dh[8 + 2 * gq]);
        float2 dx1 = __half22float2(dh[9 + 2 * gq]);
        float2 dy0 = __half22float2(dh[16 + 2 * gq]);
        float2 dy1 = __half22float2(dh[17 + 2 * gq]);

        float wgv[4] = { fmaf(f, dg0.x, wgB.x), fmaf(f, dg0.y, wgB.y),
                         fmaf(f, dg1.x, wgB.z), fmaf(f, dg1.y, wgB.w) };
        float wxv[4] = { fmaf(f, dx0.x, wxB.x), fmaf(f, dx0.y, wxB.y),
                         fmaf(f, dx1.x, wxB.z), fmaf(f, dx1.y, wxB.w) };
        float wyv[4] = { fmaf(f, dy0.x, wyB.x), fmaf(f, dy0.y, wyB.y),
                         fmaf(f, dy1.x, wyB.z), fmaf(f, dy1.y, wyB.w) };

        #pragma unroll
        for (int c4 = 0; c4 < 4; c4++) {
            float wx = wxv[c4], wy = wyv[c4];
            float wn2 = wx * wx + wy * wy;
            float one_wn2 = 1.0f - wn2;

            // h_map(zv, w)
            float dx = cz - wx, dy = sz - wy;
            float dn2 = dx * dx + dy * dy;
            float c   = __fdividef(one_wn2, dn2);
            float hzx = fmaf(c, dx, -wx);
            float hzy = fmaf(c, dy, -wy);

            // h_map((1,0), w), unscaled (atan2 is scale-invariant):
            float ex = 1.0f - wx, ey = -wy;
            float en2 = ex * ex + ey * ey;
            float h0x = one_wn2 * ex - en2 * wx;
            float h0y = one_wn2 * ey - en2 * wy;

            float cross = hzy * h0x - hzx * h0y;
            float dot   = hzx * h0x + hzy * h0y;
            float txv = fast_atan2f(cross, dot);
            if (txv < 0.0f) txv += TWO_PI;

            t_acc  = fmaf(wgv[c4], txv, t_acc);
            dt_acc = fmaf(wgv[c4], c, dt_acc);
        }
    }

    float4 m0 = q[12];
    float2 dm = __half22float2(dh[24]);
    float tr  = fmaf(f, dm.x, m0.x);
    float ldr = fmaf(f, dm.y, m0.y);

    if (idx0 < N) {
        out[idx0]         = tr;
        out[N + idx0]     = t_acc;
        out[2 * N + idx0] = ldr + __logf(dt_acc);
    }
}

// ---------------------------------------------------------------------------
extern "C" void kernel_launch(void* const* d_in, const int* in_sizes, int n_in,
                              void* d_out, int out_size) {
    const float* r  = (const float*)d_in[0];
    const float* z  = (const float*)d_in[1];
    const float* tw = (const float*)d_in[2];
    const float* th = (const float*)d_in[3];
    const float* td = (const float*)d_in[4];
    const float* W1 = (const float*)d_in[5];
    const float* b1 = (const float*)d_in[6];
    const float* W2 = (const float*)d_in[7];
    const float* b2 = (const float*)d_in[8];
    const float* W3 = (const float*)d_in[9];
    const float* b3 = (const float*)d_in[10];
    float* out = (float*)d_out;
    int N = in_sizes[0];

    int prep_blocks = (G + 1 + PTS_PER_BLOCK - 1) / PTS_PER_BLOCK;
    table_prep_kernel<<<prep_blocks, PREP_TPB>>>(
        tw, th, td, W1, b1, W2, b2, W3, b3);
    table_pack_kernel<<<(G + 255) / 256, 256>>>();
    mobius_lookup_kernel<<<(N + TPB - 1) / TPB, TPB>>>(r, z, out, N);
}

// round 16
// speedup vs baseline: 1.1518x; 1.1518x over previous
#include <cuda_runtime.h>
#include <cuda_fp16.h>
#include <cstdint>
#include <math.h>

#define KS 64
#define KM 16
#define TWO_PI 6.28318530717958647692f

#define G     32768          // grid intervals over [-1, 1]
#define TABW  96             // floats per table row (24 float4, 384B = 3 lines)
#define TABQ  24             // float4 stride per row (128B-aligned rows)

typedef unsigned long long ull;

// Packed table row (float4 units):
//  q0-3: wgt[16]  q4-7: wx[16]  q8-11: wy[16]  q12: (tr, ldr, pad, pad)
//  q13-19: fp16 deltas (wgt d0..15, wx d16..31, wy d32..47, tr d48, ldr d49)
//  q20-23: pad (never read)
__device__ __align__(16) float gTab[(G + 1) * TABW];

// ---------------- packed f32x2 helpers (Blackwell) ----------------
__device__ __forceinline__ ull pk2(float a, float b) {
    ull r; asm("mov.b64 %0, {%1,%2};" : "=l"(r) : "f"(a), "f"(b)); return r;
}
__device__ __forceinline__ void upk2(ull v, float& a, float& b) {
    asm("mov.b64 {%0,%1}, %2;" : "=f"(a), "=f"(b) : "l"(v));
}
#define FMA_X2(d, a, b, c) \
    asm("fma.rn.f32x2 %0, %1, %2, %3;" : "=l"(d) : "l"(a), "l"(b), "l"(c))
#define ADD_X2(d, a, b) \
    asm("add.rn.f32x2 %0, %1, %2;" : "=l"(d) : "l"(a), "l"(b))

__device__ __forceinline__ uint32_t smem_u32(const void* p) {
    uint32_t a;
    asm("{ .reg .u64 t; cvta.to.shared.u64 t, %1; cvt.u32.u64 %0, t; }"
        : "=r"(a) : "l"(p));
    return a;
}

// Fast atan2: octant reduction + deg-11 odd minimax (abs err ~1e-6).
__device__ __forceinline__ float fast_atan2f(float y, float x) {
    float ax = fabsf(x), ay = fabsf(y);
    float mx = fmaxf(ax, ay), mn = fminf(ax, ay);
    float a  = __fdividef(mn, mx);
    float s  = a * a;
    float p  =             -0.0117212f;
    p = fmaf(p, s,  0.05265332f);
    p = fmaf(p, s, -0.11643287f);
    p = fmaf(p, s,  0.19354346f);
    p = fmaf(p, s, -0.33262347f);
    p = fmaf(p, s,  0.99997726f);
    float r = p * a;
    if (ay > ax)  r = 1.57079632679f - r;
    if (x < 0.f)  r = 3.14159265359f - r;
    return (y < 0.f) ? -r : r;
}

// ---------------------------------------------------------------------------
// Table prep (r14 exact structure — 1 thread/point, measured 29.4us):
// every block redundantly computes the 64-knot spline tables (smem scans),
// then evaluates spline + MLP + Mobius preprocessing for its grid slice.
// ---------------------------------------------------------------------------
#define PREP_TPB 128

__global__ void __launch_bounds__(PREP_TPB, 3)
table_prep_kernel(const float* __restrict__ tw,
                  const float* __restrict__ thd,
                  const float* __restrict__ td,
                  const float* __restrict__ W1,
                  const float* __restrict__ b1,
                  const float* __restrict__ W2,
                  const float* __restrict__ b2,
                  const float* __restrict__ W3,
                  const float* __restrict__ b3) {
    __shared__ __align__(16) float sW2t[64 * 64];
    __shared__ __align__(16) float sW3[64 * 48];
    __shared__ __align__(16) float sW1[64];
    __shared__ __align__(16) float sb1[64];
    __shared__ __align__(16) float sb2[64];
    __shared__ __align__(16) float sb3[48];
    __shared__ float sxk[KS + 1], syk[KS + 1], sdv[KS + 1];
    __shared__ float scw[KS], sch[KS], stmp[KS];

    int tid = threadIdx.x;

    // ---- weights into smem ----
    for (int i = tid; i < 64 * 64; i += PREP_TPB)
        sW2t[i] = W2[(i & 63) * 64 + (i >> 6)];     // sW2t[j*64+i] = W2[i*64+j]
    for (int i = tid; i < 64 * 48; i += PREP_TPB) sW3[i] = W3[i];
    if (tid < 64) { sW1[tid] = W1[tid]; sb1[tid] = b1[tid]; sb2[tid] = b2[tid]; }
    if (tid < 48) sb3[tid] = b3[tid];

    // ---- knot tables: softmax + cumsum scans (threads 0..63) ----
    if (tid < KS) { scw[tid] = tw[tid]; sch[tid] = thd[tid]; }
    __syncthreads();
    if (tid < KS) stmp[tid] = scw[tid];
    __syncthreads();
    for (int off = 32; off > 0; off >>= 1) {
        if (tid < off) stmp[tid] = fmaxf(stmp[tid], stmp[tid + off]);
        __syncthreads();
    }
    float mw = stmp[0];
    __syncthreads();
    if (tid < KS) stmp[tid] = sch[tid];
    __syncthreads();
    for (int off = 32; off > 0; off >>= 1) {
        if (tid < off) stmp[tid] = fmaxf(stmp[tid], stmp[tid + off]);
        __syncthreads();
    }
    float mh = stmp[0];
    __syncthreads();
    if (tid < KS) { scw[tid] = expf(scw[tid] - mw); sch[tid] = expf(sch[tid] - mh); }
    __syncthreads();
    if (tid < KS) stmp[tid] = scw[tid];
    __syncthreads();
    for (int off = 32; off > 0; off >>= 1) {
        if (tid < off) stmp[tid] += stmp[tid + off];
        __syncthreads();
    }
    float sumw = stmp[0];
    __syncthreads();
    if (tid < KS) stmp[tid] = sch[tid];
    __syncthreads();
    for (int off = 32; off > 0; off >>= 1) {
        if (tid < off) stmp[tid] += stmp[tid + off];
        __syncthreads();
    }
    float sumh = stmp[0];
    __syncthreads();
    for (int off = 1; off < KS; off <<= 1) {
        float vw = 0.f, vh = 0.f;
        if (tid < KS && tid >= off) { vw = scw[tid - off]; vh = sch[tid - off]; }
        __syncthreads();
        if (tid < KS) { scw[tid] += vw; sch[tid] += vh; }
        __syncthreads();
    }
    if (tid < KS) {
        sxk[tid + 1] = fmaf(scw[tid], 2.0f / sumw, -1.0f);
        syk[tid + 1] = fmaf(sch[tid], 2.0f / sumh, -1.0f);
    }
    if (tid == 0) {
        sxk[0] = -1.0f; syk[0] = -1.0f;
        sdv[0] = 1.0f;  sdv[KS] = 1.0f;
    }
    if (tid < KS - 1) {
        float x = td[tid];
        sdv[tid + 1] = fmaxf(x, 0.f) + log1pf(expf(-fabsf(x))) + 0.001f;
    }
    __syncthreads();

    int g = blockIdx.x * PREP_TPB + tid;
    if (g > G) return;

    float r = -1.0f + 2.0f * (float)g / (float)G;

    // ---------------- spline ----------------
    int lo = 0, hi = KS + 1;
    while (lo < hi) {
        int mid = (lo + hi) >> 1;
        if (sxk[mid] < r) lo = mid + 1; else hi = mid;
    }
    int k = lo;
    if (k == 0) k = 1;
    if (k == KS + 1) k = KS;
    k -= 1;

    float xk = sxk[k], xn = sxk[k + 1];
    float yk = syk[k], yn = syk[k + 1];
    float dk = sdv[k], dnk = sdv[k + 1];
    float invw = 1.0f / (xn - xk);
    float s_k  = (yn - yk) * invw;
    float eps  = (r - xk) * invw;
    float ome  = 1.0f - eps;
    float eom  = eps * ome;
    float den  = s_k + (dnk + dk - 2.0f * s_k) * eom;
    float tr   = yk + (yn - yk) * (s_k * eps * eps + dk * eom) / den;
    float dtr  = s_k * s_k * (dnk * eps * eps + 2.0f * s_k * eom + dk * ome * ome)
                 / (den * den);

    // ---------------- MLP 1->64->64->48 (f32x2) ----------------
    ull h1p[32];
    #pragma unroll
    for (int i2 = 0; i2 < 32; i2++) {
        float a = fmaxf(fmaf(r, sW1[2 * i2],     sb1[2 * i2]),     0.0f);
        float b = fmaxf(fmaf(r, sW1[2 * i2 + 1], sb1[2 * i2 + 1]), 0.0f);
        h1p[i2] = pk2(a, b);
    }

    ull thp[24];
    const ull* b3p = (const ull*)sb3;
    #pragma unroll
    for (int t2 = 0; t2 < 24; t2++) thp[t2] = b3p[t2];

    for (int j = 0; j < 64; j++) {
        const ulonglong2* w2q = (const ulonglong2*)&sW2t[j * 64];
        ull a0 = 0ULL, a1 = 0ULL, a2 = 0ULL, a3 = 0ULL;
        #pragma unroll
        for (int q = 0; q < 8; q++) {
            ulonglong2 va = w2q[2 * q];
            ulonglong2 vb = w2q[2 * q + 1];
            FMA_X2(a0, h1p[4 * q + 0], va.x, a0);
            FMA_X2(a1, h1p[4 * q + 1], va.y, a1);
            FMA_X2(a2, h1p[4 * q + 2], vb.x, a2);
            FMA_X2(a3, h1p[4 * q + 3], vb.y, a3);
        }
        ADD_X2(a0, a0, a1);
        ADD_X2(a2, a2, a3);
        ADD_X2(a0, a0, a2);
        float s0, s1;
        upk2(a0, s0, s1);
        float h2 = fmaxf((s0 + s1) + sb2[j], 0.0f);
        ull h2p = pk2(h2, h2);

        const ulonglong2* w3q = (const ulonglong2*)&sW3[j * 48];
        #pragma unroll
        for (int q = 0; q < 12; q++) {
            ulonglong2 v = w3q[q];
            FMA_X2(thp[2 * q + 0], h2p, v.x, thp[2 * q + 0]);
            FMA_X2(thp[2 * q + 1], h2p, v.y, thp[2 * q + 1]);
        }
    }

    float th[48];
    #pragma unroll
    for (int t2 = 0; t2 < 24; t2++) upk2(thp[t2], th[2 * t2], th[2 * t2 + 1]);

    // ---------------- Mobius preprocessing ----------------
    float mx = th[0];
    #pragma unroll
    for (int t = 1; t < KM; t++) mx = fmaxf(mx, th[t]);
    float se = 0.f;
    #pragma unroll
    for (int t = 0; t < KM; t++) {
        th[t] = __expf(th[t] - mx);
        se += th[t];
    }
    float inv_se = 1.0f / se;

    float* row = &gTab[g * TABW];
    #pragma unroll
    for (int kk = 0; kk < KM; kk++) {
        float wa = th[KM + 2 * kk];
        float wb = th[KM + 2 * kk + 1];
        float nr = sqrtf(wa * wa + wb * wb);
        float s  = 0.99f / (1.0f + nr);
        row[kk]      = th[kk] * inv_se;   // wgt
        row[16 + kk] = s * wa;            // wx
        row[32 + kk] = s * wb;            // wy
    }
    row[48] = tr;
    row[49] = logf(dtr);
    row[50] = 0.f;
    row[51] = 0.f;
}

// ---------------------------------------------------------------------------
// Pack kernel: per-row fp16 deltas (row[g+1] - row[g]) into floats 52..79.
// ---------------------------------------------------------------------------
__global__ void table_pack_kernel() {
    int g = blockIdx.x * blockDim.x + threadIdx.x;
    if (g >= G) return;
    const float* a = &gTab[g * TABW];
    const float* b = &gTab[(g + 1) * TABW];
    __half2* d = (__half2*)(&gTab[g * TABW + 52]);
    #pragma unroll
    for (int e = 0; e < 25; e++) {
        float2 df;
        df.x = b[2 * e]     - a[2 * e];
        df.y = b[2 * e + 1] - a[2 * e + 1];
        d[e] = __float22half2_rn(df);
    }
    #pragma unroll
    for (int e = 25; e < 28; e++) d[e] = __half2half2(__float2half(0.f));
}

// ---------------------------------------------------------------------------
// Main kernel: per-warp SMEM staging via cp.async (20 float4 per point from
// a 128B-aligned row), base + fp16-delta lerp, Mobius with division-free h0.
// ---------------------------------------------------------------------------
#define TPB 64
#define ROWQ 21   // padded float4 stride per point in smem (20 data + 1 pad)

__global__ void __launch_bounds__(TPB)
mobius_lookup_kernel(const float* __restrict__ R,
                     const float* __restrict__ Z,
                     float* __restrict__ out,
                     int N) {
    __shared__ __align__(16) float4 sTab[TPB * ROWQ];   // 21 KB

    int tid   = threadIdx.x;
    int lane  = tid & 31;
    int wbase = tid & ~31;
    int idx0  = blockIdx.x * TPB + tid;
    int idx   = min(idx0, N - 1);

    float r = R[idx];
    float z = Z[idx];

    float u = (r + 1.0f) * ((float)G * 0.5f);
    int i = (int)floorf(u);
    i = max(0, min(G - 1, i));
    float f = u - (float)i;

    // Stage this warp's 32 points with cp.async: 20 float4 per point,
    // lane-contiguous within each point's (128B-aligned) row.
    const float4* tab4 = (const float4*)gTab;
    uint32_t sbase = smem_u32(sTab);
    #pragma unroll 10
    for (int it = 0; it < 20; it++) {
        int fl = it * 32 + lane;
        int p  = fl / 20;
        int j  = fl - p * 20;
        int ip = __shfl_sync(0xffffffffu, i, p);
        uint32_t dst = sbase + (uint32_t)(((wbase + p) * ROWQ + j) * 16);
        const float4* src = tab4 + (size_t)ip * TABQ + j;
        asm volatile("cp.async.cg.shared.global [%0], [%1], 16;"
                     :: "r"(dst), "l"(src) : "memory");
    }
    asm volatile("cp.async.commit_group;" ::: "memory");
    asm volatile("cp.async.wait_group 0;" ::: "memory");
    __syncwarp();

    const float4*  q  = &sTab[tid * ROWQ];          // q0..12 base
    const __half2* dh = (const __half2*)(q + 13);   // 28 half2 deltas

    float sz, cz;
    __sincosf(z, &sz, &cz);

    float t_acc = 0.f, dt_acc = 0.f;

    #pragma unroll
    for (int gq = 0; gq < 4; gq++) {
        float4 wgB = q[gq];
        float4 wxB = q[4 + gq];
        float4 wyB = q[8 + gq];
        float2 dg0 = __half22float2(dh[2 * gq]);
        float2 dg1 = __half22float2(dh[2 * gq + 1]);
        float2 dx0 = __half22float2(dh[8 + 2 * gq]);
        float2 dx1 = __half22float2(dh[9 + 2 * gq]);
        float2 dy0 = __half22float2(dh[16 + 2 * gq]);
        float2 dy1 = __half22float2(dh[17 + 2 * gq]);

        float wgv[4] = { fmaf(f, dg0.x, wgB.x), fmaf(f, dg0.y, wgB.y),
                         fmaf(f, dg1.x, wgB.z), fmaf(f, dg1.y, wgB.w) };
        float wxv[4] = { fmaf(f, dx0.x, wxB.x), fmaf(f, dx0.y, wxB.y),
                         fmaf(f, dx1.x, wxB.z), fmaf(f, dx1.y, wxB.w) };
        float wyv[4] = { fmaf(f, dy0.x, wyB.x), fmaf(f, dy0.y, wyB.y),
                         fmaf(f, dy1.x, wyB.z), fmaf(f, dy1.y, wyB.w) };

        #pragma unroll
        for (int c4 = 0; c4 < 4; c4++) {
            float wx = wxv[c4], wy = wyv[c4];
            float wn2 = wx * wx + wy * wy;
            float one_wn2 = 1.0f - wn2;

            // h_map(zv, w)
            float dx = cz - wx, dy = sz - wy;
            float dn2 = dx * dx + dy * dy;
            float c   = __fdividef(one_wn2, dn2);
            float hzx = fmaf(c, dx, -wx);
            float hzy = fmaf(c, dy, -wy);

            // h_map((1,0), w), unscaled (atan2 is scale-invariant):
            float ex = 1.0f - wx, ey = -wy;
            float en2 = ex * ex + ey * ey;
            float h0x = one_wn2 * ex - en2 * wx;
            float h0y = one_wn2 * ey - en2 * wy;

            float cross = hzy * h0x - hzx * h0y;
            float dot   = hzx * h0x + hzy * h0y;
            float txv = fast_atan2f(cross, dot);
            if (txv < 0.0f) txv += TWO_PI;

            t_acc  = fmaf(wgv[c4], txv, t_acc);
            dt_acc = fmaf(wgv[c4], c, dt_acc);
        }
    }

    float4 m0 = q[12];
    float2 dm = __half22float2(dh[24]);
    float tr  = fmaf(f, dm.x, m0.x);
    float ldr = fmaf(f, dm.y, m0.y);

    if (idx0 < N) {
        out[idx0]         = tr;
        out[N + idx0]     = t_acc;
        out[2 * N + idx0] = ldr + __logf(dt_acc);
    }
}

// ---------------------------------------------------------------------------
extern "C" void kernel_launch(void* const* d_in, const int* in_sizes, int n_in,
                              void* d_out, int out_size) {
    const float* r  = (const float*)d_in[0];
    const float* z  = (const float*)d_in[1];
    const float* tw = (const float*)d_in[2];
    const float* th = (const float*)d_in[3];
    const float* td = (const float*)d_in[4];
    const float* W1 = (const float*)d_in[5];
    const float* b1 = (const float*)d_in[6];
    const float* W2 = (const float*)d_in[7];
    const float* b2 = (const float*)d_in[8];
    const float* W3 = (const float*)d_in[9];
    const float* b3 = (const float*)d_in[10];
    float* out = (float*)d_out;
    int N = in_sizes[0];

    table_prep_kernel<<<(G + PREP_TPB) / PREP_TPB, PREP_TPB>>>(
        tw, th, td, W1, b1, W2, b2, W3, b3);
    table_pack_kernel<<<(G + 255) / 256, 256>>>();
    mobius_lookup_kernel<<<(N + TPB - 1) / TPB, TPB>>>(r, z, out, N);
}

// round 17
// speedup vs baseline: 1.2121x; 1.0523x over previous
#include <cuda_runtime.h>
#include <cuda_fp16.h>
#include <cstdint>
#include <math.h>

#define KS 64
#define KM 16
#define TWO_PI 6.28318530717958647692f

#define G     32768          // grid intervals over [-1, 1]
#define TABW  80             // floats per table row: 52 base + 28 delta(fp16x2)
#define TABQ  20             // float4 per row

typedef unsigned long long ull;

// Packed table row (float4 units):
//  q0-3: wgt[16]  q4-7: wx[16]  q8-11: wy[16]  q12: (tr, ldr, pad, pad)
//  q13-19: fp16 deltas (wgt d0..15, wx d16..31, wy d32..47, tr d48, ldr d49)
__device__ __align__(16) float gTab[(G + 1) * TABW];

// ---------------- packed f32x2 helpers (Blackwell) ----------------
__device__ __forceinline__ ull pk2(float a, float b) {
    ull r; asm("mov.b64 %0, {%1,%2};" : "=l"(r) : "f"(a), "f"(b)); return r;
}
__device__ __forceinline__ void upk2(ull v, float& a, float& b) {
    asm("mov.b64 {%0,%1}, %2;" : "=f"(a), "=f"(b) : "l"(v));
}
#define FMA_X2(d, a, b, c) \
    asm("fma.rn.f32x2 %0, %1, %2, %3;" : "=l"(d) : "l"(a), "l"(b), "l"(c))
#define ADD_X2(d, a, b) \
    asm("add.rn.f32x2 %0, %1, %2;" : "=l"(d) : "l"(a), "l"(b))

__device__ __forceinline__ uint32_t smem_u32(const void* p) {
    uint32_t a;
    asm("{ .reg .u64 t; cvta.to.shared.u64 t, %1; cvt.u32.u64 %0, t; }"
        : "=r"(a) : "l"(p));
    return a;
}

// Fast atan2: octant reduction + deg-11 odd minimax (abs err ~1e-6).
__device__ __forceinline__ float fast_atan2f(float y, float x) {
    float ax = fabsf(x), ay = fabsf(y);
    float mx = fmaxf(ax, ay), mn = fminf(ax, ay);
    float a  = __fdividef(mn, mx);
    float s  = a * a;
    float p  =             -0.0117212f;
    p = fmaf(p, s,  0.05265332f);
    p = fmaf(p, s, -0.11643287f);
    p = fmaf(p, s,  0.19354346f);
    p = fmaf(p, s, -0.33262347f);
    p = fmaf(p, s,  0.99997726f);
    float r = p * a;
    if (ay > ax)  r = 1.57079632679f - r;
    if (x < 0.f)  r = 3.14159265359f - r;
    return (y < 0.f) ? -r : r;
}

// ---------------------------------------------------------------------------
// Table prep, GEMM-tiled: 48 points per 96-thread block.
//  Phase 1: H1[64][48] in smem (relu(W1 r + b1))
//  Phase 2: H2[64][48] = relu(W2^T H1 + b2)   (thread tile 4j x 8p, f32x2)
//  Phase 3: TH[48 pts][48 t] = W3^T H2 + b3   (thread tile 4t x 8p)
//  Postproc: thread-per-point spline + softmax + w-norms -> gTab row.
// Weight reuse across 48 points cuts smem crossbar traffic ~6x vs 1-thr/pt.
// ---------------------------------------------------------------------------
#define PREP_TPB 96
#define PTS 48

__global__ void __launch_bounds__(PREP_TPB)
table_prep_kernel(const float* __restrict__ tw,
                  const float* __restrict__ thd,
                  const float* __restrict__ td,
                  const float* __restrict__ W1,
                  const float* __restrict__ b1,
                  const float* __restrict__ W2,
                  const float* __restrict__ b2,
                  const float* __restrict__ W3,
                  const float* __restrict__ b3) {
    __shared__ __align__(16) float sA[64 * 64];    // W2 rows, later W3 rows
    __shared__ __align__(16) float sH1[64 * PTS];  // H1, later TH[48][52]
    __shared__ __align__(16) float sH2[64 * PTS];
    __shared__ __align__(16) float sW1[64];
    __shared__ __align__(16) float sb1[64];
    __shared__ __align__(16) float sb2[64];
    __shared__ __align__(16) float sb3[48];
    __shared__ float sxk[KS + 1], syk[KS + 1], sdv[KS + 1];
    __shared__ float scw[KS], sch[KS], stmp[KS];

    int tid = threadIdx.x;
    int g0  = blockIdx.x * PTS;

    // ---- load W2 (linear) + small arrays ----
    for (int i = tid; i < 64 * 64; i += PREP_TPB) sA[i] = W2[i];
    if (tid < 64) { sW1[tid] = W1[tid]; sb1[tid] = b1[tid]; sb2[tid] = b2[tid]; }
    if (tid < 48) sb3[tid] = b3[tid];

    // ---- knot tables: softmax + cumsum scans (threads 0..63) ----
    if (tid < KS) { scw[tid] = tw[tid]; sch[tid] = thd[tid]; }
    __syncthreads();
    if (tid < KS) stmp[tid] = scw[tid];
    __syncthreads();
    for (int off = 32; off > 0; off >>= 1) {
        if (tid < off) stmp[tid] = fmaxf(stmp[tid], stmp[tid + off]);
        __syncthreads();
    }
    float mw = stmp[0];
    __syncthreads();
    if (tid < KS) stmp[tid] = sch[tid];
    __syncthreads();
    for (int off = 32; off > 0; off >>= 1) {
        if (tid < off) stmp[tid] = fmaxf(stmp[tid], stmp[tid + off]);
        __syncthreads();
    }
    float mh = stmp[0];
    __syncthreads();
    if (tid < KS) { scw[tid] = expf(scw[tid] - mw); sch[tid] = expf(sch[tid] - mh); }
    __syncthreads();
    if (tid < KS) stmp[tid] = scw[tid];
    __syncthreads();
    for (int off = 32; off > 0; off >>= 1) {
        if (tid < off) stmp[tid] += stmp[tid + off];
        __syncthreads();
    }
    float sumw = stmp[0];
    __syncthreads();
    if (tid < KS) stmp[tid] = sch[tid];
    __syncthreads();
    for (int off = 32; off > 0; off >>= 1) {
        if (tid < off) stmp[tid] += stmp[tid + off];
        __syncthreads();
    }
    float sumh = stmp[0];
    __syncthreads();
    for (int off = 1; off < KS; off <<= 1) {
        float vw = 0.f, vh = 0.f;
        if (tid < KS && tid >= off) { vw = scw[tid - off]; vh = sch[tid - off]; }
        __syncthreads();
        if (tid < KS) { scw[tid] += vw; sch[tid] += vh; }
        __syncthreads();
    }
    if (tid < KS) {
        sxk[tid + 1] = fmaf(scw[tid], 2.0f / sumw, -1.0f);
        syk[tid + 1] = fmaf(sch[tid], 2.0f / sumh, -1.0f);
    }
    if (tid == 0) {
        sxk[0] = -1.0f; syk[0] = -1.0f;
        sdv[0] = 1.0f;  sdv[KS] = 1.0f;
    }
    if (tid < KS - 1) {
        float x = td[tid];
        sdv[tid + 1] = fmaxf(x, 0.f) + log1pf(expf(-fabsf(x))) + 0.001f;
    }
    __syncthreads();

    // ---- Phase 1: H1[i][p] ----
    {
        int p  = tid % PTS;
        int ih = tid / PTS;          // 0 or 1
        int g  = min(g0 + p, G);
        float r = -1.0f + 2.0f * (float)g / (float)G;
        #pragma unroll 8
        for (int m = 0; m < 32; m++) {
            int i = ih * 32 + m;
            sH1[i * PTS + p] = fmaxf(fmaf(r, sW1[i], sb1[i]), 0.0f);
        }
    }
    __syncthreads();

    // ---- Phase 2: H2 = relu(W2^T H1 + b2), tile 4j x 8p ----
    {
        int tj = tid & 15;           // 0..15 -> j = 4*tj..
        int tp = tid >> 4;           // 0..5  -> p = 8*tp..
        ull acc[4][4];
        #pragma unroll
        for (int a = 0; a < 4; a++)
            #pragma unroll
            for (int b = 0; b < 4; b++) acc[a][b] = 0ULL;

        #pragma unroll 8
        for (int i = 0; i < 64; i++) {
            float4 w  = *(const float4*)&sA[i * 64 + tj * 4];
            float4 hA = *(const float4*)&sH1[i * PTS + tp * 8];
            float4 hB = *(const float4*)&sH1[i * PTS + tp * 8 + 4];
            ull hp0 = pk2(hA.x, hA.y), hp1 = pk2(hA.z, hA.w);
            ull hp2 = pk2(hB.x, hB.y), hp3 = pk2(hB.z, hB.w);
            ull w0 = pk2(w.x, w.x), w1 = pk2(w.y, w.y);
            ull w2v = pk2(w.z, w.z), w3v = pk2(w.w, w.w);
            FMA_X2(acc[0][0], w0, hp0, acc[0][0]);
            FMA_X2(acc[0][1], w0, hp1, acc[0][1]);
            FMA_X2(acc[0][2], w0, hp2, acc[0][2]);
            FMA_X2(acc[0][3], w0, hp3, acc[0][3]);
            FMA_X2(acc[1][0], w1, hp0, acc[1][0]);
            FMA_X2(acc[1][1], w1, hp1, acc[1][1]);
            FMA_X2(acc[1][2], w1, hp2, acc[1][2]);
            FMA_X2(acc[1][3], w1, hp3, acc[1][3]);
            FMA_X2(acc[2][0], w2v, hp0, acc[2][0]);
            FMA_X2(acc[2][1], w2v, hp1, acc[2][1]);
            FMA_X2(acc[2][2], w2v, hp2, acc[2][2]);
            FMA_X2(acc[2][3], w2v, hp3, acc[2][3]);
            FMA_X2(acc[3][0], w3v, hp0, acc[3][0]);
            FMA_X2(acc[3][1], w3v, hp1, acc[3][1]);
            FMA_X2(acc[3][2], w3v, hp2, acc[3][2]);
            FMA_X2(acc[3][3], w3v, hp3, acc[3][3]);
        }

        #pragma unroll
        for (int jj = 0; jj < 4; jj++) {
            int j = tj * 4 + jj;
            float bb = sb2[j];
            float v0, v1, v2, v3, v4, v5, v6, v7;
            upk2(acc[jj][0], v0, v1);
            upk2(acc[jj][1], v2, v3);
            upk2(acc[jj][2], v4, v5);
            upk2(acc[jj][3], v6, v7);
            float4 o0 = make_float4(fmaxf(v0 + bb, 0.f), fmaxf(v1 + bb, 0.f),
                                    fmaxf(v2 + bb, 0.f), fmaxf(v3 + bb, 0.f));
            float4 o1 = make_float4(fmaxf(v4 + bb, 0.f), fmaxf(v5 + bb, 0.f),
                                    fmaxf(v6 + bb, 0.f), fmaxf(v7 + bb, 0.f));
            *(float4*)&sH2[j * PTS + tp * 8]     = o0;
            *(float4*)&sH2[j * PTS + tp * 8 + 4] = o1;
        }
    }
    __syncthreads();

    // ---- load W3 over W2's buffer (stride 48, linear) ----
    for (int i = tid; i < 64 * 48; i += PREP_TPB) sA[i] = W3[i];
    __syncthreads();

    // ---- Phase 3: TH = W3^T H2 + b3, tile 4t x 8p; TH overlays sH1 ----
    float* sTH = sH1;   // [p][52], 48*52 <= 64*48
    {
        int tt = tid & 15;           // active if < 12
        int tp = tid >> 4;
        if (tt < 12) {
            ull acc3[4][4];
            #pragma unroll
            for (int a = 0; a < 4; a++)
                #pragma unroll
                for (int b = 0; b < 4; b++) acc3[a][b] = 0ULL;

            #pragma unroll 8
            for (int j = 0; j < 64; j++) {
                float4 w  = *(const float4*)&sA[j * 48 + tt * 4];
                float4 hA = *(const float4*)&sH2[j * PTS + tp * 8];
                float4 hB = *(const float4*)&sH2[j * PTS + tp * 8 + 4];
                ull hp0 = pk2(hA.x, hA.y), hp1 = pk2(hA.z, hA.w);
                ull hp2 = pk2(hB.x, hB.y), hp3 = pk2(hB.z, hB.w);
                ull w0 = pk2(w.x, w.x), w1 = pk2(w.y, w.y);
                ull w2v = pk2(w.z, w.z), w3v = pk2(w.w, w.w);
                FMA_X2(acc3[0][0], w0, hp0, acc3[0][0]);
                FMA_X2(acc3[0][1], w0, hp1, acc3[0][1]);
                FMA_X2(acc3[0][2], w0, hp2, acc3[0][2]);
                FMA_X2(acc3[0][3], w0, hp3, acc3[0][3]);
                FMA_X2(acc3[1][0], w1, hp0, acc3[1][0]);
                FMA_X2(acc3[1][1], w1, hp1, acc3[1][1]);
                FMA_X2(acc3[1][2], w1, hp2, acc3[1][2]);
                FMA_X2(acc3[1][3], w1, hp3, acc3[1][3]);
                FMA_X2(acc3[2][0], w2v, hp0, acc3[2][0]);
                FMA_X2(acc3[2][1], w2v, hp1, acc3[2][1]);
                FMA_X2(acc3[2][2], w2v, hp2, acc3[2][2]);
                FMA_X2(acc3[2][3], w2v, hp3, acc3[2][3]);
                FMA_X2(acc3[3][0], w3v, hp0, acc3[3][0]);
                FMA_X2(acc3[3][1], w3v, hp1, acc3[3][1]);
                FMA_X2(acc3[3][2], w3v, hp2, acc3[3][2]);
                FMA_X2(acc3[3][3], w3v, hp3, acc3[3][3]);
            }

            float v[4][8];
            #pragma unroll
            for (int ttt = 0; ttt < 4; ttt++) {
                float bv = sb3[tt * 4 + ttt];
                upk2(acc3[ttt][0], v[ttt][0], v[ttt][1]);
                upk2(acc3[ttt][1], v[ttt][2], v[ttt][3]);
                upk2(acc3[ttt][2], v[ttt][4], v[ttt][5]);
                upk2(acc3[ttt][3], v[ttt][6], v[ttt][7]);
                #pragma unroll
                for (int m = 0; m < 8; m++) v[ttt][m] += bv;
            }
            #pragma unroll
            for (int pp = 0; pp < 8; pp++) {
                float4 o = make_float4(v[0][pp], v[1][pp], v[2][pp], v[3][pp]);
                *(float4*)&sTH[(tp * 8 + pp) * 52 + tt * 4] = o;
            }
        }
    }
    __syncthreads();

    // ---- Postproc: thread-per-point ----
    if (tid < PTS) {
        int p = tid;
        int g = min(g0 + p, G);
        float r = -1.0f + 2.0f * (float)g / (float)G;

        // spline
        int lo = 0, hi = KS + 1;
        while (lo < hi) {
            int mid = (lo + hi) >> 1;
            if (sxk[mid] < r) lo = mid + 1; else hi = mid;
        }
        int k = lo;
        if (k == 0) k = 1;
        if (k == KS + 1) k = KS;
        k -= 1;
        float xk = sxk[k], xn = sxk[k + 1];
        float yk = syk[k], yn = syk[k + 1];
        float dk = sdv[k], dnk = sdv[k + 1];
        float invw = 1.0f / (xn - xk);
        float s_k  = (yn - yk) * invw;
        float eps  = (r - xk) * invw;
        float ome  = 1.0f - eps;
        float eom  = eps * ome;
        float den  = s_k + (dnk + dk - 2.0f * s_k) * eom;
        float tr   = yk + (yn - yk) * (s_k * eps * eps + dk * eom) / den;
        float dtr  = s_k * s_k * (dnk * eps * eps + 2.0f * s_k * eom + dk * ome * ome)
                     / (den * den);

        float th[48];
        const float4* thq = (const float4*)&sTH[p * 52];
        #pragma unroll
        for (int q = 0; q < 12; q++) {
            float4 vq = thq[q];
            th[4 * q]     = vq.x;
            th[4 * q + 1] = vq.y;
            th[4 * q + 2] = vq.z;
            th[4 * q + 3] = vq.w;
        }

        float mx2 = th[0];
        #pragma unroll
        for (int t = 1; t < KM; t++) mx2 = fmaxf(mx2, th[t]);
        float se = 0.f;
        #pragma unroll
        for (int t = 0; t < KM; t++) {
            th[t] = __expf(th[t] - mx2);
            se += th[t];
        }
        float inv_se = 1.0f / se;

        float* row = &gTab[g * TABW];
        #pragma unroll
        for (int kk = 0; kk < KM; kk++) {
            float wa = th[KM + 2 * kk];
            float wb = th[KM + 2 * kk + 1];
            float nr = sqrtf(wa * wa + wb * wb);
            float sc = 0.99f / (1.0f + nr);
            row[kk]      = th[kk] * inv_se;
            row[16 + kk] = sc * wa;
            row[32 + kk] = sc * wb;
        }
        row[48] = tr;
        row[49] = logf(dtr);
        row[50] = 0.f;
        row[51] = 0.f;
    }
}

// ---------------------------------------------------------------------------
// Pack kernel: per-row fp16 deltas (row[g+1] - row[g]) into floats 52..79.
// ---------------------------------------------------------------------------
__global__ void table_pack_kernel() {
    int g = blockIdx.x * blockDim.x + threadIdx.x;
    if (g >= G) return;
    const float* a = &gTab[g * TABW];
    const float* b = &gTab[(g + 1) * TABW];
    __half2* d = (__half2*)(&gTab[g * TABW + 52]);
    #pragma unroll
    for (int e = 0; e < 25; e++) {
        float2 df;
        df.x = b[2 * e]     - a[2 * e];
        df.y = b[2 * e + 1] - a[2 * e + 1];
        d[e] = __float22half2_rn(df);
    }
    #pragma unroll
    for (int e = 25; e < 28; e++) d[e] = __half2half2(__float2half(0.f));
}

// ---------------------------------------------------------------------------
// Main kernel (exact r14 81.9us version): per-warp SMEM staging via cp.async,
// base + fp16-delta lerp, Mobius with division-free h0.
// ---------------------------------------------------------------------------
#define TPB 64
#define ROWQ 21   // padded float4 stride per point in smem (20 data + 1 pad)

__global__ void __launch_bounds__(TPB)
mobius_lookup_kernel(const float* __restrict__ R,
                     const float* __restrict__ Z,
                     float* __restrict__ out,
                     int N) {
    __shared__ __align__(16) float4 sTab[TPB * ROWQ];   // 21 KB

    int tid   = threadIdx.x;
    int lane  = tid & 31;
    int wbase = tid & ~31;
    int idx0  = blockIdx.x * TPB + tid;
    int idx   = min(idx0, N - 1);

    float r = R[idx];
    float z = Z[idx];

    float u = (r + 1.0f) * ((float)G * 0.5f);
    int i = (int)floorf(u);
    i = max(0, min(G - 1, i));
    float f = u - (float)i;

    const float4* tab4 = (const float4*)gTab;
    uint32_t sbase = smem_u32(sTab);
    #pragma unroll 10
    for (int it = 0; it < 20; it++) {
        int fl = it * 32 + lane;
        int p  = fl / 20;
        int j  = fl - p * 20;
        int ip = __shfl_sync(0xffffffffu, i, p);
        uint32_t dst = sbase + (uint32_t)(((wbase + p) * ROWQ + j) * 16);
        const float4* src = tab4 + (size_t)ip * TABQ + j;
        asm volatile("cp.async.cg.shared.global [%0], [%1], 16;"
                     :: "r"(dst), "l"(src) : "memory");
    }
    asm volatile("cp.async.commit_group;" ::: "memory");
    asm volatile("cp.async.wait_group 0;" ::: "memory");
    __syncwarp();

    const float4*  q  = &sTab[tid * ROWQ];
    const __half2* dh = (const __half2*)(q + 13);

    float sz, cz;
    __sincosf(z, &sz, &cz);

    float t_acc = 0.f, dt_acc = 0.f;

    #pragma unroll
    for (int gq = 0; gq < 4; gq++) {
        float4 wgB = q[gq];
        float4 wxB = q[4 + gq];
        float4 wyB = q[8 + gq];
        float2 dg0 = __half22float2(dh[2 * gq]);
        float2 dg1 = __half22float2(dh[2 * gq + 1]);
        float2 dx0 = __half22float2(dh[8 + 2 * gq]);
        float2 dx1 = __half22float2(dh[9 + 2 * gq]);
        float2 dy0 = __half22float2(dh[16 + 2 * gq]);
        float2 dy1 = __half22float2(dh[17 + 2 * gq]);

        float wgv[4] = { fmaf(f, dg0.x, wgB.x), fmaf(f, dg0.y, wgB.y),
                         fmaf(f, dg1.x, wgB.z), fmaf(f, dg1.y, wgB.w) };
        float wxv[4] = { fmaf(f, dx0.x, wxB.x), fmaf(f, dx0.y, wxB.y),
                         fmaf(f, dx1.x, wxB.z), fmaf(f, dx1.y, wxB.w) };
        float wyv[4] = { fmaf(f, dy0.x, wyB.x), fmaf(f, dy0.y, wyB.y),
                         fmaf(f, dy1.x, wyB.z), fmaf(f, dy1.y, wyB.w) };

        #pragma unroll
        for (int c4 = 0; c4 < 4; c4++) {
            float wx = wxv[c4], wy = wyv[c4];
            float wn2 = wx * wx + wy * wy;
            float one_wn2 = 1.0f - wn2;

            float dx = cz - wx, dy = sz - wy;
            float dn2 = dx * dx + dy * dy;
            float c   = __fdividef(one_wn2, dn2);
            float hzx = fmaf(c, dx, -wx);
            float hzy = fmaf(c, dy, -wy);

            float ex = 1.0f - wx, ey = -wy;
            float en2 = ex * ex + ey * ey;
            float h0x = one_wn2 * ex - en2 * wx;
            float h0y = one_wn2 * ey - en2 * wy;

            float cross = hzy * h0x - hzx * h0y;
            float dot   = hzx * h0x + hzy * h0y;
            float txv = fast_atan2f(cross, dot);
            if (txv < 0.0f) txv += TWO_PI;

            t_acc  = fmaf(wgv[c4], txv, t_acc);
            dt_acc = fmaf(wgv[c4], c, dt_acc);
        }
    }

    float4 m0 = q[12];
    float2 dm = __half22float2(dh[24]);
    float tr  = fmaf(f, dm.x, m0.x);
    float ldr = fmaf(f, dm.y, m0.y);

    if (idx0 < N) {
        out[idx0]         = tr;
        out[N + idx0]     = t_acc;
        out[2 * N + idx0] = ldr + __logf(dt_acc);
    }
}

// ---------------------------------------------------------------------------
extern "C" void kernel_launch(void* const* d_in, const int* in_sizes, int n_in,
                              void* d_out, int out_size) {
    const float* r  = (const float*)d_in[0];
    const float* z  = (const float*)d_in[1];
    const float* tw = (const float*)d_in[2];
    const float* th = (const float*)d_in[3];
    const float* td = (const float*)d_in[4];
    const float* W1 = (const float*)d_in[5];
    const float* b1 = (const float*)d_in[6];
    const float* W2 = (const float*)d_in[7];
    const float* b2 = (const float*)d_in[8];
    const float* W3 = (const float*)d_in[9];
    const float* b3 = (const float*)d_in[10];
    float* out = (float*)d_out;
    int N = in_sizes[0];

    int prep_blocks = (G + 1 + PTS - 1) / PTS;
    table_prep_kernel<<<prep_blocks, PREP_TPB>>>(
        tw, th, td, W1, b1, W2, b2, W3, b3);
    table_pack_kernel<<<(G + 255) / 256, 256>>>();
    mobius_lookup_kernel<<<(N + TPB - 1) / TPB, TPB>>>(r, z, out, N);
}